// round 12
// baseline (speedup 1.0000x reference)
#include <cuda_runtime.h>

#define BH_TOTAL (1024 * 32)
#define NNB  25
#define KTOT 26
#define FDIM 128
#define DDIM 128
#define NTHREADS 512
#define GRID 296          // 2 CTAs per SM, single wave

#define TILE_BYTES  (KTOT * FDIM * 4)   // 13312
#define SELF_BYTES  (FDIM * 4)          // 512
#define NEIGH_BYTES (NNB * FDIM * 4)    // 12800

__device__ __align__(16) float g_u_self[FDIM];
__device__ __align__(16) float g_u_neigh[FDIM];

__global__ void precompute_u_kernel(const float* __restrict__ w,
                                    const float* __restrict__ a_self,
                                    const float* __restrict__ a_neigh) {
    int t = threadIdx.x;
    if (t < FDIM) {
        float s = 0.f;
        #pragma unroll 8
        for (int d = 0; d < DDIM; d++) s = fmaf(w[t * DDIM + d], a_self[d], s);
        g_u_self[t] = s;
    } else if (t < 2 * FDIM) {
        int f = t - FDIM;
        float s = 0.f;
        #pragma unroll 8
        for (int d = 0; d < DDIM; d++) s = fmaf(w[f * DDIM + d], a_neigh[d], s);
        g_u_neigh[f] = s;
    }
}

// ---- TMA bulk + mbarrier helpers (identical to the proven R3 kernel) ----
__device__ __forceinline__ void mbar_init(unsigned mbar, unsigned count) {
    asm volatile("mbarrier.init.shared.b64 [%0], %1;" :: "r"(mbar), "r"(count) : "memory");
}
__device__ __forceinline__ void mbar_expect_tx(unsigned mbar, unsigned tx) {
    asm volatile("mbarrier.arrive.expect_tx.shared.b64 _, [%0], %1;"
                 :: "r"(mbar), "r"(tx) : "memory");
}
__device__ __forceinline__ void mbar_wait(unsigned mbar, unsigned parity) {
    asm volatile(
        "{\n\t"
        ".reg .pred p;\n\t"
        "WAIT_%=:\n\t"
        "mbarrier.try_wait.parity.acquire.cta.shared::cta.b64 p, [%0], %1, 0x989680;\n\t"
        "@!p bra WAIT_%=;\n\t"
        "}"
        :: "r"(mbar), "r"(parity) : "memory");
}
__device__ __forceinline__ void tma_bulk_g2s(unsigned dst_smem, const void* src_gmem,
                                             unsigned bytes, unsigned mbar) {
    asm volatile(
        "cp.async.bulk.shared::cta.global.mbarrier::complete_tx::bytes [%0], [%1], %2, [%3];"
        :: "r"(dst_smem), "l"(src_gmem), "r"(bytes), "r"(mbar) : "memory");
}
__device__ __forceinline__ void fence_proxy_async_sc() {
    asm volatile("fence.proxy.async.shared::cta;" ::: "memory");
}

__device__ __forceinline__ float dot4(float4 a, float4 b) {
    float s = a.x * b.x;
    s = fmaf(a.y, b.y, s);
    s = fmaf(a.z, b.z, s);
    s = fmaf(a.w, b.w, s);
    return s;
}
__device__ __forceinline__ float xor_reduce(float v) {
    #pragma unroll
    for (int o = 16; o; o >>= 1)
        v += __shfl_xor_sync(0xffffffffu, v, o);
    return v;
}

__global__ __launch_bounds__(NTHREADS, 2)
void gat_agg_kernel(const float* __restrict__ x_self,
                    const float* __restrict__ x_neigh,
                    const float* __restrict__ w,
                    float* __restrict__ out) {
    __shared__ __align__(128) float xs[2][KTOT * FDIM];  // double-buffered tile
    __shared__ __align__(16)  float part_sm[4][FDIM];    // aggregate partials
    __shared__ float s_raw[32];
    __shared__ __align__(8) unsigned long long mbar[2];

    const int tid   = threadIdx.x;
    const int lane  = tid & 31;
    const int warp  = tid >> 5;
    const int grp   = warp >> 2;        // warp-uniform k-group, 0..3 (== tid>>7)
    const int dcol  = tid & 127;        // coalesced column for aggregate
    const int g     = tid & 3;          // matvec f-group (lane-level, LDS only)
    const int d_own = tid >> 2;         // matvec output column

    // W slice in registers: wreg[i] = W[32*g + i][d_own]
    float wreg[32];
    #pragma unroll
    for (int i = 0; i < 32; i++)
        wreg[i] = w[(32 * g + i) * DDIM + d_own];

    // attention projection vectors in registers (lane-mapped float4)
    const float4 un4 = ((const float4*)g_u_neigh)[lane];
    const float4 us4 = ((const float4*)g_u_self)[lane];

    const unsigned mb0  = (unsigned)__cvta_generic_to_shared(&mbar[0]);
    const unsigned mb1  = (unsigned)__cvta_generic_to_shared(&mbar[1]);
    const unsigned xsa0 = (unsigned)__cvta_generic_to_shared(xs[0]);
    const unsigned xsa1 = (unsigned)__cvta_generic_to_shared(xs[1]);

    if (tid == 0) {
        mbar_init(mb0, 1);
        mbar_init(mb1, 1);
        fence_proxy_async_sc();
    }
    __syncthreads();

    long bh = blockIdx.x;
    // ---- Prologue: TMA tile 0 into buffer 0 ----
    if (tid == 0) {
        mbar_expect_tx(mb0, TILE_BYTES);
        tma_bulk_g2s(xsa0, x_self + bh * FDIM, SELF_BYTES, mb0);
        tma_bulk_g2s(xsa0 + SELF_BYTES, x_neigh + bh * (NNB * FDIM),
                     NEIGH_BYTES, mb0);
    }

    int buf = 0;
    unsigned ph0 = 0, ph1 = 0;
    for (; bh < BH_TOTAL; bh += GRID) {
        // ---- [sync 1] wait current tile; all threads past previous tile ----
        if (buf == 0) { mbar_wait(mb0, ph0); ph0 ^= 1; }
        else          { mbar_wait(mb1, ph1); ph1 ^= 1; }
        __syncthreads();

        // ---- Prefetch next tile into other buffer ----
        const long nbh = bh + GRID;
        if (nbh < BH_TOTAL && tid == 0) {
            const unsigned nmb  = buf ? mb0 : mb1;
            const unsigned ndst = buf ? xsa0 : xsa1;
            mbar_expect_tx(nmb, TILE_BYTES);
            tma_bulk_g2s(ndst, x_self + nbh * FDIM, SELF_BYTES, nmb);
            tma_bulk_g2s(ndst + SELF_BYTES, x_neigh + nbh * (NNB * FDIM),
                         NEIGH_BYTES, nmb);
        }

        const float* xt = xs[buf];

        // ---- Scores: 27 warp-tasks over 16 warps, u in registers ----
        for (int task = warp; task < 27; task += 16) {
            const int row = (task == 26) ? 0 : task;
            const float4 xv = ((const float4*)(xt + row * FDIM))[lane];
            const float4 uv = (task == 26) ? us4 : un4;
            const float s = xor_reduce(dot4(xv, uv));
            if (lane == 0) s_raw[task] = s;
        }
        __syncthreads();   // [sync 2]

        // ---- Softmax over 26 entries, redundantly per warp ----
        const float ss = s_raw[26];
        float v = (lane < KTOT) ? (ss + s_raw[lane]) : -3.0e38f;
        v = (v > 0.f) ? v : 0.2f * v;                    // leaky_relu(0.2)
        float m = v;
        #pragma unroll
        for (int o = 16; o; o >>= 1)
            m = fmaxf(m, __shfl_xor_sync(0xffffffffu, m, o));
        const float ex   = (lane < KTOT) ? __expf(v - m) : 0.f;
        const float inv  = 1.f / xor_reduce(ex);
        const float attn = ex * inv;                     // lane k: weight k (0 if k>=26)

        // ---- Aggregate: 4-way k-split, grp warp-uniform, coalesced LDS ----
        {
            float acc = 0.f;
            #pragma unroll
            for (int jj = 0; jj < 7; jj++) {
                const int k = grp + 4 * jj;              // warp-uniform
                if (k < KTOT) {                          // warp-uniform branch
                    const float wk = __shfl_sync(0xffffffffu, attn, k); // full-warp
                    acc = fmaf(wk, xt[k * FDIM + dcol], acc);
                }
            }
            part_sm[grp][dcol] = acc;
        }
        __syncthreads();   // [sync 3]

        // ---- Matvec with inline 4-part sum; bank-rotation conflict-free ----
        float r = 0.f;
        #pragma unroll
        for (int i = 0; i < 8; i++) {
            const int ii = (i + 2 * g) & 7;
            const int off = 32 * g + 4 * ii;             // word offset into a part row
            const float4 p0 = *(const float4*)(part_sm[0] + off);
            const float4 p1 = *(const float4*)(part_sm[1] + off);
            const float4 p2 = *(const float4*)(part_sm[2] + off);
            const float4 p3 = *(const float4*)(part_sm[3] + off);
            const float vx = (p0.x + p1.x) + (p2.x + p3.x);
            const float vy = (p0.y + p1.y) + (p2.y + p3.y);
            const float vz = (p0.z + p1.z) + (p2.z + p3.z);
            const float vw = (p0.w + p1.w) + (p2.w + p3.w);
            r = fmaf(vx, wreg[4 * ii + 0], r);
            r = fmaf(vy, wreg[4 * ii + 1], r);
            r = fmaf(vz, wreg[4 * ii + 2], r);
            r = fmaf(vw, wreg[4 * ii + 3], r);
        }
        r += __shfl_xor_sync(0xffffffffu, r, 1);
        r += __shfl_xor_sync(0xffffffffu, r, 2);
        if (g == 0)
            out[bh * DDIM + d_own] = fmaxf(r, 0.f);
        // part_sm/s_raw reuse next tile is ordered by syncs 1+2 of that tile.

        buf ^= 1;
    }
}

extern "C" void kernel_launch(void* const* d_in, const int* in_sizes, int n_in,
                              void* d_out, int out_size) {
    const float* x_self  = (const float*)d_in[0];
    const float* x_neigh = (const float*)d_in[1];
    const float* w_feat  = (const float*)d_in[2];
    const float* a_self  = (const float*)d_in[3];
    const float* a_neigh = (const float*)d_in[4];
    float* out = (float*)d_out;

    precompute_u_kernel<<<1, 256>>>(w_feat, a_self, a_neigh);
    gat_agg_kernel<<<GRID, NTHREADS>>>(x_self, x_neigh, w_feat, out);
}

// round 14
// speedup vs baseline: 1.9949x; 1.9949x over previous
#include <cuda_runtime.h>

#define BH_TOTAL (1024 * 32)
#define NNB  25
#define KTOT 26
#define FDIM 128
#define DDIM 128
#define NTHREADS 512
#define GRID 148            // 1 CTA per SM
#define TB   8              // tiles per batch

#define TILE_FLOATS (KTOT * FDIM)       // 3328
#define TILE_BYTES  (TILE_FLOATS * 4)   // 13312
#define SELF_BYTES  (FDIM * 4)          // 512
#define NEIGH_BYTES (NNB * FDIM * 4)    // 12800

// dynamic smem layout
#define SM_TILES_BYTES (2 * TB * TILE_BYTES)            // 212992
#define SM_XAGG_OFF    (SM_TILES_BYTES)                 // 8*128 floats
#define SM_SRAW_OFF    (SM_XAGG_OFF + TB * FDIM * 4)    // 8*32 floats
#define SM_MBAR_OFF    (SM_SRAW_OFF + TB * 32 * 4)
#define SM_TOTAL       (SM_MBAR_OFF + 2 * 8)            // 218128

__device__ __align__(16) float g_u_self[FDIM];
__device__ __align__(16) float g_u_neigh[FDIM];

__global__ void precompute_u_kernel(const float* __restrict__ w,
                                    const float* __restrict__ a_self,
                                    const float* __restrict__ a_neigh) {
    int t = threadIdx.x;
    if (t < FDIM) {
        float s = 0.f;
        #pragma unroll 8
        for (int d = 0; d < DDIM; d++) s = fmaf(w[t * DDIM + d], a_self[d], s);
        g_u_self[t] = s;
    } else if (t < 2 * FDIM) {
        int f = t - FDIM;
        float s = 0.f;
        #pragma unroll 8
        for (int d = 0; d < DDIM; d++) s = fmaf(w[f * DDIM + d], a_neigh[d], s);
        g_u_neigh[f] = s;
    }
}

// ---- TMA bulk + mbarrier helpers (proven in R3) ----
__device__ __forceinline__ void mbar_init(unsigned mbar, unsigned count) {
    asm volatile("mbarrier.init.shared.b64 [%0], %1;" :: "r"(mbar), "r"(count) : "memory");
}
__device__ __forceinline__ void mbar_expect_tx(unsigned mbar, unsigned tx) {
    asm volatile("mbarrier.arrive.expect_tx.shared.b64 _, [%0], %1;"
                 :: "r"(mbar), "r"(tx) : "memory");
}
__device__ __forceinline__ void mbar_wait(unsigned mbar, unsigned parity) {
    asm volatile(
        "{\n\t"
        ".reg .pred p;\n\t"
        "WAIT_%=:\n\t"
        "mbarrier.try_wait.parity.acquire.cta.shared::cta.b64 p, [%0], %1, 0x989680;\n\t"
        "@!p bra WAIT_%=;\n\t"
        "}"
        :: "r"(mbar), "r"(parity) : "memory");
}
__device__ __forceinline__ void tma_bulk_g2s(unsigned dst_smem, const void* src_gmem,
                                             unsigned bytes, unsigned mbar) {
    asm volatile(
        "cp.async.bulk.shared::cta.global.mbarrier::complete_tx::bytes [%0], [%1], %2, [%3];"
        :: "r"(dst_smem), "l"(src_gmem), "r"(bytes), "r"(mbar) : "memory");
}
__device__ __forceinline__ void fence_proxy_async_sc() {
    asm volatile("fence.proxy.async.shared::cta;" ::: "memory");
}

__device__ __forceinline__ float dot4(float4 a, float4 b) {
    float s = a.x * b.x;
    s = fmaf(a.y, b.y, s);
    s = fmaf(a.z, b.z, s);
    s = fmaf(a.w, b.w, s);
    return s;
}
__device__ __forceinline__ float xor_reduce(float v) {
    #pragma unroll
    for (int o = 16; o; o >>= 1)
        v += __shfl_xor_sync(0xffffffffu, v, o);
    return v;
}

// tid0-only: prefetch batch pb (valid tiles only) into half pb&1
__device__ __forceinline__ void prefetch_batch(int pb, int ntiles, int cta,
                                               unsigned tiles_sa, const unsigned* mbs,
                                               const float* x_self, const float* x_neigh) {
    const int nv = min(TB, ntiles - pb * TB);
    const unsigned mb = mbs[pb & 1];
    mbar_expect_tx(mb, (unsigned)(nv * TILE_BYTES));
    for (int e = 0; e < nv; e++) {
        const long bh = (long)cta + (long)(pb * TB + e) * GRID;
        const unsigned dst = tiles_sa + ((pb & 1) * TB + e) * TILE_BYTES;
        tma_bulk_g2s(dst, x_self + bh * FDIM, SELF_BYTES, mb);
        tma_bulk_g2s(dst + SELF_BYTES, x_neigh + bh * (NNB * FDIM), NEIGH_BYTES, mb);
    }
}

__global__ __launch_bounds__(NTHREADS, 1)
void gat_agg_kernel(const float* __restrict__ x_self,
                    const float* __restrict__ x_neigh,
                    const float* __restrict__ w,
                    float* __restrict__ out) {
    extern __shared__ __align__(128) char smem_raw[];
    float* tiles = (float*)smem_raw;                       // [2*TB][3328]
    float* xagg  = (float*)(smem_raw + SM_XAGG_OFF);       // [TB][128]
    float* sraw  = (float*)(smem_raw + SM_SRAW_OFF);       // [TB][32]
    unsigned long long* mbar = (unsigned long long*)(smem_raw + SM_MBAR_OFF);

    const int tid   = threadIdx.x;
    const int lane  = tid & 31;
    const int warp  = tid >> 5;
    const int g     = tid & 3;          // matvec f-group
    const int d_own = tid >> 2;         // matvec output column

    // W slice in registers: wreg[i] = W[32*g + i][d_own]
    float wreg[32];
    #pragma unroll
    for (int i = 0; i < 32; i++)
        wreg[i] = w[(32 * g + i) * DDIM + d_own];

    const float4 un4 = ((const float4*)g_u_neigh)[lane];
    const float4 us4 = ((const float4*)g_u_self)[lane];

    const int cta    = blockIdx.x;
    const int ntiles = (BH_TOTAL - 1 - cta) / GRID + 1;
    const int nbatch = (ntiles + TB - 1) / TB;

    unsigned mbs[2];
    mbs[0] = (unsigned)__cvta_generic_to_shared(&mbar[0]);
    mbs[1] = (unsigned)__cvta_generic_to_shared(&mbar[1]);
    const unsigned tiles_sa = (unsigned)__cvta_generic_to_shared(tiles);

    if (tid == 0) {
        mbar_init(mbs[0], 1);
        mbar_init(mbs[1], 1);
        fence_proxy_async_sc();
    }
    __syncthreads();

    // ---- Prologue: prefetch batches 0 and 1 ----
    if (tid == 0) {
        prefetch_batch(0, ntiles, cta, tiles_sa, mbs, x_self, x_neigh);
        if (1 < nbatch)
            prefetch_batch(1, ntiles, cta, tiles_sa, mbs, x_self, x_neigh);
    }

    for (int b = 0; b < nbatch; b++) {
        const int h = b & 1;
        mbar_wait(mbs[h], (unsigned)((b >> 1) & 1));
        __syncthreads();                               // [sync 1]

        const int nbv = min(TB, ntiles - b * TB);
        const float* base = tiles + h * TB * TILE_FLOATS;

        // ---- Phase A: scores — nbv*27 independent warp-tasks ----
        const int ntasks = nbv * 27;
        for (int t = warp; t < ntasks; t += 16) {
            const int e   = t / 27;
            const int sub = t - e * 27;
            const int row = (sub == 26) ? 0 : sub;
            const float4 xv = ((const float4*)(base + e * TILE_FLOATS + row * FDIM))[lane];
            const float4 uv = (sub == 26) ? us4 : un4;
            const float s = xor_reduce(dot4(xv, uv));
            if (lane == 0) sraw[e * 32 + sub] = s;
        }
        __syncthreads();                               // [sync 2]

        // ---- Phase B: warp e owns tile e — softmax + aggregate, no cross-warp deps ----
        if (warp < nbv) {
            const int e = warp;
            const float* xt = base + e * TILE_FLOATS;
            const float ss = sraw[e * 32 + 26];
            float v = (lane < KTOT) ? (ss + sraw[e * 32 + lane]) : -3.0e38f;
            v = (v > 0.f) ? v : 0.2f * v;              // leaky_relu(0.2)
            float m = v;
            #pragma unroll
            for (int o = 16; o; o >>= 1)
                m = fmaxf(m, __shfl_xor_sync(0xffffffffu, m, o));
            const float ex   = (lane < KTOT) ? __expf(v - m) : 0.f;
            const float inv  = 1.f / xor_reduce(ex);
            const float attn = ex * inv;               // lane k holds weight k

            float4 acc = make_float4(0.f, 0.f, 0.f, 0.f);
            #pragma unroll
            for (int k = 0; k < KTOT; k++) {
                const float wk = __shfl_sync(0xffffffffu, attn, k);
                const float4 xv = ((const float4*)(xt + k * FDIM))[lane];
                acc.x = fmaf(wk, xv.x, acc.x);
                acc.y = fmaf(wk, xv.y, acc.y);
                acc.z = fmaf(wk, xv.z, acc.z);
                acc.w = fmaf(wk, xv.w, acc.w);
            }
            ((float4*)(xagg + e * FDIM))[lane] = acc;
        }
        __syncthreads();                               // [sync 3] — tile buffers free

        // ---- Prefetch batch b+2 into this half (buffers just freed) ----
        if (tid == 0 && b + 2 < nbatch)
            prefetch_batch(b + 2, ntiles, cta, tiles_sa, mbs, x_self, x_neigh);

        // ---- Phase C: batched matvec vs register-resident W (8 LDS/thread/tile) ----
        #pragma unroll 1
        for (int e = 0; e < nbv; e++) {
            const long bh = (long)cta + (long)(b * TB + e) * GRID;
            const float4* xa = (const float4*)(xagg + e * FDIM + 32 * g);
            float r = 0.f;
            #pragma unroll
            for (int i = 0; i < 8; i++) {
                const int ii = (i + 2 * g) & 7;        // conflict-free rotation
                const float4 vv = xa[ii];
                r = fmaf(vv.x, wreg[4 * ii + 0], r);
                r = fmaf(vv.y, wreg[4 * ii + 1], r);
                r = fmaf(vv.z, wreg[4 * ii + 2], r);
                r = fmaf(vv.w, wreg[4 * ii + 3], r);
            }
            r += __shfl_xor_sync(0xffffffffu, r, 1);
            r += __shfl_xor_sync(0xffffffffu, r, 2);
            if (g == 0)
                out[bh * DDIM + d_own] = fmaxf(r, 0.f);
        }
        // next batch's sync1+sync2 order xagg/sraw reuse against this Phase C
    }
}

extern "C" void kernel_launch(void* const* d_in, const int* in_sizes, int n_in,
                              void* d_out, int out_size) {
    const float* x_self  = (const float*)d_in[0];
    const float* x_neigh = (const float*)d_in[1];
    const float* w_feat  = (const float*)d_in[2];
    const float* a_self  = (const float*)d_in[3];
    const float* a_neigh = (const float*)d_in[4];
    float* out = (float*)d_out;

    cudaFuncSetAttribute(gat_agg_kernel,
                         cudaFuncAttributeMaxDynamicSharedMemorySize, SM_TOTAL);

    precompute_u_kernel<<<1, 256>>>(w_feat, a_self, a_neigh);
    gat_agg_kernel<<<GRID, NTHREADS, SM_TOTAL>>>(x_self, x_neigh, w_feat, out);
}